// round 5
// baseline (speedup 1.0000x reference)
#include <cuda_runtime.h>
#include <math.h>

// RenderNet volume rendering — round 5: two-kernel split + persistent balanced
// composite with atomic tile queue.
// Shapes: B=1, C=32, Z=64, N=Y*X=65536.
// feat [C,Z,N] f32, occ [Z,N] f32, z_dist [Z], noise [N,Z] f32.
// out: [0]=loss, [1..1+CN)=rgb_e, [1+CN..1+2CN)=feat_e, [..+N)=acc_e (4B-aligned
// only -> scalar stores on outputs).
//
// K1: one thread per ray. Computes weights w[z][n] -> g_wbuf (16MB, coalesced
//     stores; stays L2-resident for K2), acc_map, loss. Resets tile counter.
// K2: persistent, grid=592 CTAs x 256 thr (4/SM -> one wave). Tile queue of
//     2048 tiles, tile = 256 rays x 4 channels => 1KB contiguous per (c,z)
//     stream (DRAM-row friendly). Thread = 1 channel x 4 rays: per z one
//     LDG.128 feat (.cs streaming) + one LDG.128 weights (L2 hit), unroll 4.

#define RN_C 32
#define RN_Z 64
#define RN_N 65536
#define RAW_NOISE_STD 0.1f
#define FAR_DIST 1e10f

#define K2_GRID 592          // 4 CTAs/SM * 148 SMs
#define K2_THREADS 256
#define TILE_RAYS 256
#define TILE_CH 4
#define NUM_TILES ((RN_N / TILE_RAYS) * (RN_C / TILE_CH))   // 256*8 = 2048

__device__ float g_wbuf[RN_Z * RN_N];     // weights [z][n], 16MB
__device__ unsigned int g_tile_ctr;

// ---------------- K1: weights ----------------
__global__ void __launch_bounds__(256)
rn_weights(const float* __restrict__ occ,
           const float* __restrict__ z_dist,
           const float* __restrict__ noise,
           float* __restrict__ out)
{
    __shared__ float s_dist[RN_Z];
    const int tid = threadIdx.x;
    if (tid < RN_Z)
        s_dist[tid] = (tid < RN_Z - 1) ? (z_dist[tid + 1] - z_dist[tid]) : FAR_DIST;
    __syncthreads();

    const int n = blockIdx.x * blockDim.x + tid;

    const float4* np4 = (const float4*)(noise + (size_t)n * RN_Z);
    const float* occp = occ + n;

    float trans = 1.0f;
    float wsum  = 0.0f;
#pragma unroll
    for (int zq = 0; zq < RN_Z / 4; ++zq) {
        float4 nz4 = __ldcs(np4 + zq);
        float nzv[4] = {nz4.x, nz4.y, nz4.z, nz4.w};
#pragma unroll
        for (int j = 0; j < 4; ++j) {
            int z = zq * 4 + j;
            float o   = __ldcs(occp + (size_t)z * RN_N);
            float raw = fmaxf(fmaf(nzv[j], RAW_NOISE_STD, o), 0.0f);
            float alpha = 1.0f - expf(-raw * s_dist[z]);
            float w = alpha * trans;
            trans *= (1.0f - alpha + 1e-10f);
            wsum  += w;
            g_wbuf[(size_t)z * RN_N + n] = w;   // coalesced; lands in L2
        }
    }
    float* am = out + 1 + 2 * (size_t)RN_C * RN_N;
    am[n] = fminf(fmaxf(wsum, 0.0f), 1.0f);

    if (n == 0) {
        out[0] = 0.0f;
        g_tile_ctr = 0;          // reset queue for K2 (kernel-boundary ordered)
    }
}

// ---------------- K2: persistent composite ----------------
__global__ void __launch_bounds__(K2_THREADS)
rn_composite(const float* __restrict__ feat,
             float* __restrict__ out)
{
    __shared__ int s_tile;

    const int tid  = threadIdx.x;
    const int quad = tid & 63;     // 64 ray-quads -> 256 rays
    const int ci   = tid >> 6;     // 0..3 channel within tile

    float* rgb = out + 1;
    float* fe  = out + 1 + (size_t)RN_C * RN_N;

    for (;;) {
        __syncthreads();
        if (tid == 0) s_tile = (int)atomicAdd(&g_tile_ctr, 1u);
        __syncthreads();
        const int t = s_tile;
        if (t >= NUM_TILES) break;

        const int rb = t >> 3;              // ray block 0..255
        const int cq = t & 7;               // channel quad 0..7
        const int c  = cq * TILE_CH + ci;   // channel 0..31
        const int n0 = rb * TILE_RAYS + quad * 4;

        const float* fp = feat + ((size_t)c * RN_Z) * RN_N + n0;
        const float* wp = g_wbuf + n0;

        float4 a = {0.f, 0.f, 0.f, 0.f};
#pragma unroll 4
        for (int z = 0; z < RN_Z; ++z) {
            float4 w = __ldg((const float4*)(wp + (size_t)z * RN_N)); // L2 hit
            float4 v = __ldcs((const float4*)(fp + (size_t)z * RN_N));
            a.x = fmaf(w.x, v.x, a.x);
            a.y = fmaf(w.y, v.y, a.y);
            a.z = fmaf(w.z, v.z, a.z);
            a.w = fmaf(w.w, v.w, a.w);
        }

        const size_t o0 = (size_t)c * RN_N + n0;
        float av[4] = {a.x, a.y, a.z, a.w};
#pragma unroll
        for (int j = 0; j < 4; ++j) {
            fe[o0 + j]  = av[j];
            rgb[o0 + j] = 1.0f / (1.0f + expf(-av[j])) - 0.5f;
        }
    }
}

// ---------------- generic fallback (any Z/N) ----------------
__global__ void __launch_bounds__(256)
rendernet_generic(const float* __restrict__ feat,
                  const float* __restrict__ occ,
                  const float* __restrict__ z_dist,
                  const float* __restrict__ noise,
                  float* __restrict__ out,
                  int Z, int N)
{
    extern __shared__ float s_d[];
    int tid = threadIdx.x;
    if (tid < Z)
        s_d[tid] = (tid < Z - 1) ? (z_dist[tid + 1] - z_dist[tid]) : FAR_DIST;
    __syncthreads();

    int n = blockIdx.x * blockDim.x + tid;
    if (n >= N) return;

    float acc[RN_C];
#pragma unroll
    for (int c = 0; c < RN_C; ++c) acc[c] = 0.0f;

    const float* occp   = occ + n;
    const float* noisep = noise + (size_t)n * Z;
    const float* featp  = feat + n;
    const size_t ZN = (size_t)Z * (size_t)N;

    float trans = 1.0f, wsum = 0.0f;
    for (int z = 0; z < Z; ++z) {
        float raw = fmaxf(fmaf(noisep[z], RAW_NOISE_STD, occp[(size_t)z * N]), 0.0f);
        float alpha = 1.0f - expf(-raw * s_d[z]);
        float w = alpha * trans;
        trans *= (1.0f - alpha + 1e-10f);
        wsum += w;
        const float* fz = featp + (size_t)z * N;
#pragma unroll
        for (int c = 0; c < RN_C; ++c)
            acc[c] = fmaf(w, fz[(size_t)c * ZN], acc[c]);
    }
    float* rgb = out + 1;
    float* fe  = out + 1 + (size_t)RN_C * N;
    float* am  = out + 1 + 2 * (size_t)RN_C * N;
#pragma unroll
    for (int c = 0; c < RN_C; ++c) {
        float f = acc[c];
        fe[(size_t)c * N + n]  = f;
        rgb[(size_t)c * N + n] = 1.0f / (1.0f + expf(-f)) - 0.5f;
    }
    am[n] = fminf(fmaxf(wsum, 0.0f), 1.0f);
    if (n == 0) out[0] = 0.0f;
}

extern "C" void kernel_launch(void* const* d_in, const int* in_sizes, int n_in,
                              void* d_out, int out_size)
{
    const float* feat   = (const float*)d_in[0];
    const float* occ    = (const float*)d_in[1];
    const float* z_dist = (const float*)d_in[2];
    const float* noise  = (const float*)d_in[3];
    float* out = (float*)d_out;

    int Z = in_sizes[2];
    int N = in_sizes[1] / Z;

    if (Z == RN_Z && N == RN_N) {
        rn_weights<<<RN_N / 256, 256>>>(occ, z_dist, noise, out);
        rn_composite<<<K2_GRID, K2_THREADS>>>(feat, out);
    } else {
        int block = 256;
        int grid = (N + block - 1) / block;
        rendernet_generic<<<grid, block, Z * sizeof(float)>>>(feat, occ, z_dist, noise, out, Z, N);
    }
}

// round 6
// speedup vs baseline: 1.0343x; 1.0343x over previous
#include <cuda_runtime.h>
#include <math.h>

// RenderNet volume rendering — round 6: balanced split, no queue.
// Shapes: B=1, C=32, Z=64, N=Y*X=65536.
// feat [C,Z,N] f32, occ [Z,N] f32, z_dist [Z], noise [N,Z] f32.
// out: [0]=loss, [1..1+CN)=rgb_e, [1+CN..1+2CN)=feat_e, [..+N)=acc_e
// (out+1 only 4B-aligned -> scalar output stores).
//
// K1 (weights): grid 1024 x 64 thr, one ray/thread (balanced ~7 CTA/SM).
//     Writes w[z][n] to g_wbuf (16MB; L2-resident for K2) + acc_map + loss.
// K2 (composite): grid 740 x 256 thr (5 CTAs/SM via launch_bounds -> 40
//     warps/SM, single wave). Static grid-stride over 524288 jobs; job =
//     4 rays x 1 channel full-z column: per z one LDG.128 feat (.cs) +
//     one LDG.128 weights (L2 hit), z unrolled 4 (8 LDG.128 in flight).
//     Warp = 32 consecutive quads -> 512B contiguous per (c,z).

#define RN_C 32
#define RN_Z 64
#define RN_N 65536
#define RAW_NOISE_STD 0.1f
#define FAR_DIST 1e10f

#define K2_GRID 740           // 5 CTAs/SM * 148 SMs
#define K2_THREADS 256
#define K2_JOBS (RN_C * (RN_N / 4))   // 32 * 16384 = 524288

__device__ float g_wbuf[RN_Z * RN_N];   // weights [z][n], 16MB

// ---------------- K1: weights ----------------
__global__ void __launch_bounds__(64)
rn_weights(const float* __restrict__ occ,
           const float* __restrict__ z_dist,
           const float* __restrict__ noise,
           float* __restrict__ out)
{
    __shared__ float s_dist[RN_Z];
    const int tid = threadIdx.x;
    s_dist[tid] = (tid < RN_Z - 1) ? (z_dist[tid + 1] - z_dist[tid]) : FAR_DIST;
    __syncthreads();

    const int n = blockIdx.x * 64 + tid;

    const float4* np4 = (const float4*)(noise + (size_t)n * RN_Z);
    const float* occp = occ + n;

    float trans = 1.0f;
    float wsum  = 0.0f;
#pragma unroll
    for (int zq = 0; zq < RN_Z / 4; ++zq) {
        float4 nz4 = __ldcs(np4 + zq);
        float nzv[4] = {nz4.x, nz4.y, nz4.z, nz4.w};
#pragma unroll
        for (int j = 0; j < 4; ++j) {
            int z = zq * 4 + j;
            float o   = __ldcs(occp + (size_t)z * RN_N);
            float raw = fmaxf(fmaf(nzv[j], RAW_NOISE_STD, o), 0.0f);
            float alpha = 1.0f - expf(-raw * s_dist[z]);
            float w = alpha * trans;
            trans *= (1.0f - alpha + 1e-10f);
            wsum  += w;
            g_wbuf[(size_t)z * RN_N + n] = w;   // coalesced; L2-resident
        }
    }
    float* am = out + 1 + 2 * (size_t)RN_C * RN_N;
    am[n] = fminf(fmaxf(wsum, 0.0f), 1.0f);
    if (n == 0) out[0] = 0.0f;
}

// ---------------- K2: composite (static grid-stride) ----------------
__global__ void __launch_bounds__(K2_THREADS, 5)
rn_composite(const float* __restrict__ feat,
             float* __restrict__ out)
{
    const int gtid = blockIdx.x * K2_THREADS + threadIdx.x;
    const int nthr = K2_GRID * K2_THREADS;

    float* rgb = out + 1;
    float* fe  = out + 1 + (size_t)RN_C * RN_N;
    const size_t ZN = (size_t)RN_Z * (size_t)RN_N;

    for (int jj = gtid; jj < K2_JOBS; jj += nthr) {
        const int c  = jj >> 14;            // channel 0..31
        const int q  = jj & 16383;          // ray quad 0..16383
        const int n0 = q * 4;

        const float* fp = feat + (size_t)c * ZN + n0;
        const float* wp = g_wbuf + n0;

        float4 a = {0.f, 0.f, 0.f, 0.f};
#pragma unroll 4
        for (int z = 0; z < RN_Z; ++z) {
            float4 w = __ldg((const float4*)(wp + (size_t)z * RN_N));  // L2 hit
            float4 v = __ldcs((const float4*)(fp + (size_t)z * RN_N)); // stream
            a.x = fmaf(w.x, v.x, a.x);
            a.y = fmaf(w.y, v.y, a.y);
            a.z = fmaf(w.z, v.z, a.z);
            a.w = fmaf(w.w, v.w, a.w);
        }

        const size_t o0 = (size_t)c * RN_N + n0;
        float av[4] = {a.x, a.y, a.z, a.w};
#pragma unroll
        for (int j = 0; j < 4; ++j) {
            fe[o0 + j]  = av[j];
            rgb[o0 + j] = 1.0f / (1.0f + expf(-av[j])) - 0.5f;
        }
    }
}

// ---------------- generic fallback (any Z/N) ----------------
__global__ void __launch_bounds__(256)
rendernet_generic(const float* __restrict__ feat,
                  const float* __restrict__ occ,
                  const float* __restrict__ z_dist,
                  const float* __restrict__ noise,
                  float* __restrict__ out,
                  int Z, int N)
{
    extern __shared__ float s_d[];
    int tid = threadIdx.x;
    if (tid < Z)
        s_d[tid] = (tid < Z - 1) ? (z_dist[tid + 1] - z_dist[tid]) : FAR_DIST;
    __syncthreads();

    int n = blockIdx.x * blockDim.x + tid;
    if (n >= N) return;

    float acc[RN_C];
#pragma unroll
    for (int c = 0; c < RN_C; ++c) acc[c] = 0.0f;

    const float* occp   = occ + n;
    const float* noisep = noise + (size_t)n * Z;
    const float* featp  = feat + n;
    const size_t ZN = (size_t)Z * (size_t)N;

    float trans = 1.0f, wsum = 0.0f;
    for (int z = 0; z < Z; ++z) {
        float raw = fmaxf(fmaf(noisep[z], RAW_NOISE_STD, occp[(size_t)z * N]), 0.0f);
        float alpha = 1.0f - expf(-raw * s_d[z]);
        float w = alpha * trans;
        trans *= (1.0f - alpha + 1e-10f);
        wsum += w;
        const float* fz = featp + (size_t)z * N;
#pragma unroll
        for (int c = 0; c < RN_C; ++c)
            acc[c] = fmaf(w, fz[(size_t)c * ZN], acc[c]);
    }
    float* rgb = out + 1;
    float* fe  = out + 1 + (size_t)RN_C * N;
    float* am  = out + 1 + 2 * (size_t)RN_C * N;
#pragma unroll
    for (int c = 0; c < RN_C; ++c) {
        float f = acc[c];
        fe[(size_t)c * N + n]  = f;
        rgb[(size_t)c * N + n] = 1.0f / (1.0f + expf(-f)) - 0.5f;
    }
    am[n] = fminf(fmaxf(wsum, 0.0f), 1.0f);
    if (n == 0) out[0] = 0.0f;
}

extern "C" void kernel_launch(void* const* d_in, const int* in_sizes, int n_in,
                              void* d_out, int out_size)
{
    const float* feat   = (const float*)d_in[0];
    const float* occ    = (const float*)d_in[1];
    const float* z_dist = (const float*)d_in[2];
    const float* noise  = (const float*)d_in[3];
    float* out = (float*)d_out;

    int Z = in_sizes[2];
    int N = in_sizes[1] / Z;

    if (Z == RN_Z && N == RN_N) {
        rn_weights<<<RN_N / 64, 64>>>(occ, z_dist, noise, out);
        rn_composite<<<K2_GRID, K2_THREADS>>>(feat, out);
    } else {
        int block = 256;
        int grid = (N + block - 1) / block;
        rendernet_generic<<<grid, block, Z * sizeof(float)>>>(feat, occ, z_dist, noise, out, Z, N);
    }
}

// round 7
// speedup vs baseline: 1.3725x; 1.3270x over previous
#include <cuda_runtime.h>
#include <math.h>

// RenderNet volume rendering — round 7.
// K1: thread-per-ray weights with CHUNKED PREFETCH (16 indep occ loads + 4
//     noise float4 batched ahead of each 16-step recurrence segment -> MLP 16).
// K2: single-wave static composite; warp = 4 channels x 8 ray-quads so the
//     weight LDG.128 is one shared 128B line per warp (4x less L2 traffic);
//     feat loads = 4 x 128B fully-used segments per request.
// out: [0]=loss, [1..1+CN)=rgb_e, [1+CN..1+2CN)=feat_e, [..+N)=acc_e
// (out+1 only 4B-aligned -> scalar output stores).

#define RN_C 32
#define RN_Z 64
#define RN_N 65536
#define RAW_NOISE_STD 0.1f
#define FAR_DIST 1e10f

#define K2_GRID 740            // 5 CTAs/SM * 148 SMs, single wave
#define K2_THREADS 256
#define K2_NWARPS (K2_GRID * K2_THREADS / 32)       // 5920
#define K2_WARPJOBS ((RN_C / 4) * (RN_N / 4 / 8))   // 8 * 2048 = 16384

__device__ float g_wbuf[RN_Z * RN_N];   // weights [z][n], 16MB (L2-resident)

// ---------------- K1: weights, chunked prefetch ----------------
__global__ void __launch_bounds__(64)
rn_weights(const float* __restrict__ occ,
           const float* __restrict__ z_dist,
           const float* __restrict__ noise,
           float* __restrict__ out)
{
    __shared__ float s_dist[RN_Z];
    const int tid = threadIdx.x;
    s_dist[tid] = (tid < RN_Z - 1) ? (z_dist[tid + 1] - z_dist[tid]) : FAR_DIST;
    __syncthreads();

    const int n = blockIdx.x * 64 + tid;
    const float4* np4 = (const float4*)(noise + (size_t)n * RN_Z);
    const float*  occp = occ + n;

    float trans = 1.0f;
    float wsum  = 0.0f;

#pragma unroll
    for (int zc = 0; zc < RN_Z / 16; ++zc) {        // 4 chunks of 16 z
        // ---- batch-load: 16 independent occ + 16 noise (4 x float4) ----
        float ov[16];
#pragma unroll
        for (int j = 0; j < 16; ++j)
            ov[j] = __ldcs(occp + (size_t)(zc * 16 + j) * RN_N);
        float4 nq[4];
#pragma unroll
        for (int j = 0; j < 4; ++j)
            nq[j] = __ldcs(np4 + zc * 4 + j);
        float nv[16];
#pragma unroll
        for (int j = 0; j < 4; ++j) {
            nv[j * 4 + 0] = nq[j].x; nv[j * 4 + 1] = nq[j].y;
            nv[j * 4 + 2] = nq[j].z; nv[j * 4 + 3] = nq[j].w;
        }
        // ---- 16 recurrence steps from registers ----
#pragma unroll
        for (int j = 0; j < 16; ++j) {
            int z = zc * 16 + j;
            float raw = fmaxf(fmaf(nv[j], RAW_NOISE_STD, ov[j]), 0.0f);
            float alpha = 1.0f - expf(-raw * s_dist[z]);
            float w = alpha * trans;
            trans *= (1.0f - alpha + 1e-10f);
            wsum  += w;
            g_wbuf[(size_t)z * RN_N + n] = w;      // coalesced
        }
    }

    float* am = out + 1 + 2 * (size_t)RN_C * RN_N;
    am[n] = fminf(fmaxf(wsum, 0.0f), 1.0f);
    if (n == 0) out[0] = 0.0f;
}

// ---------------- K2: composite, warp-shared weights ----------------
__global__ void __launch_bounds__(K2_THREADS, 5)
rn_composite(const float* __restrict__ feat,
             float* __restrict__ out)
{
    const int wid0 = (blockIdx.x * K2_THREADS + threadIdx.x) >> 5; // global warp
    const int lane = threadIdx.x & 31;
    const int c2   = lane >> 3;     // 0..3 channel within group
    const int q8   = lane & 7;      // 0..7 quad within group

    float* rgb = out + 1;
    float* fe  = out + 1 + (size_t)RN_C * RN_N;
    const size_t ZN = (size_t)RN_Z * (size_t)RN_N;

    for (int wj = wid0; wj < K2_WARPJOBS; wj += K2_NWARPS) {
        const int cg = wj >> 11;               // 0..7 channel group
        const int qg = wj & 2047;              // 0..2047 quad group
        const int c  = cg * 4 + c2;            // channel 0..31
        const int n0 = (qg * 8 + q8) * 4;      // ray start

        const float* fp = feat + (size_t)c * ZN + n0;
        const float* wp = g_wbuf + n0;

        float4 a = {0.f, 0.f, 0.f, 0.f};
#pragma unroll 4
        for (int z = 0; z < RN_Z; ++z) {
            float4 w = __ldg((const float4*)(wp + (size_t)z * RN_N));  // 1 line/warp
            float4 v = __ldcs((const float4*)(fp + (size_t)z * RN_N)); // stream
            a.x = fmaf(w.x, v.x, a.x);
            a.y = fmaf(w.y, v.y, a.y);
            a.z = fmaf(w.z, v.z, a.z);
            a.w = fmaf(w.w, v.w, a.w);
        }

        const size_t o0 = (size_t)c * RN_N + n0;
        float av[4] = {a.x, a.y, a.z, a.w};
#pragma unroll
        for (int j = 0; j < 4; ++j) {
            fe[o0 + j]  = av[j];
            rgb[o0 + j] = 1.0f / (1.0f + expf(-av[j])) - 0.5f;
        }
    }
}

// ---------------- generic fallback (any Z/N) ----------------
__global__ void __launch_bounds__(256)
rendernet_generic(const float* __restrict__ feat,
                  const float* __restrict__ occ,
                  const float* __restrict__ z_dist,
                  const float* __restrict__ noise,
                  float* __restrict__ out,
                  int Z, int N)
{
    extern __shared__ float s_d[];
    int tid = threadIdx.x;
    if (tid < Z)
        s_d[tid] = (tid < Z - 1) ? (z_dist[tid + 1] - z_dist[tid]) : FAR_DIST;
    __syncthreads();

    int n = blockIdx.x * blockDim.x + tid;
    if (n >= N) return;

    float acc[RN_C];
#pragma unroll
    for (int c = 0; c < RN_C; ++c) acc[c] = 0.0f;

    const float* occp   = occ + n;
    const float* noisep = noise + (size_t)n * Z;
    const float* featp  = feat + n;
    const size_t ZN = (size_t)Z * (size_t)N;

    float trans = 1.0f, wsum = 0.0f;
    for (int z = 0; z < Z; ++z) {
        float raw = fmaxf(fmaf(noisep[z], RAW_NOISE_STD, occp[(size_t)z * N]), 0.0f);
        float alpha = 1.0f - expf(-raw * s_d[z]);
        float w = alpha * trans;
        trans *= (1.0f - alpha + 1e-10f);
        wsum += w;
        const float* fz = featp + (size_t)z * N;
#pragma unroll
        for (int c = 0; c < RN_C; ++c)
            acc[c] = fmaf(w, fz[(size_t)c * ZN], acc[c]);
    }
    float* rgb = out + 1;
    float* fe  = out + 1 + (size_t)RN_C * N;
    float* am  = out + 1 + 2 * (size_t)RN_C * N;
#pragma unroll
    for (int c = 0; c < RN_C; ++c) {
        float f = acc[c];
        fe[(size_t)c * N + n]  = f;
        rgb[(size_t)c * N + n] = 1.0f / (1.0f + expf(-f)) - 0.5f;
    }
    am[n] = fminf(fmaxf(wsum, 0.0f), 1.0f);
    if (n == 0) out[0] = 0.0f;
}

extern "C" void kernel_launch(void* const* d_in, const int* in_sizes, int n_in,
                              void* d_out, int out_size)
{
    const float* feat   = (const float*)d_in[0];
    const float* occ    = (const float*)d_in[1];
    const float* z_dist = (const float*)d_in[2];
    const float* noise  = (const float*)d_in[3];
    float* out = (float*)d_out;

    int Z = in_sizes[2];
    int N = in_sizes[1] / Z;

    if (Z == RN_Z && N == RN_N) {
        rn_weights<<<RN_N / 64, 64>>>(occ, z_dist, noise, out);
        rn_composite<<<K2_GRID, K2_THREADS>>>(feat, out);
    } else {
        int block = 256;
        int grid = (N + block - 1) / block;
        rendernet_generic<<<grid, block, Z * sizeof(float)>>>(feat, occ, z_dist, noise, out, Z, N);
    }
}